// round 15
// baseline (speedup 1.0000x reference)
#include <cuda_runtime.h>
#include <cuda_fp16.h>
#include <cstdint>

// Problem dims (fixed)
#define N_Q   8192
#define M_KV  8192
#define D_IN  1024
#define D_OUT 1024

// GEMM tiling (fp16 operands), 4 warps of 64x64
#define BM 128
#define BN 128
#define BK 64                          // halves per k-slab = 128 bytes/row
#define NTHREADS 128
#define AST 36                         // smem row stride in 32-bit words (32 data + 4 pad)
#define SLAB_WORDS (BM * AST)
#define STAGE_WORDS (2 * SLAB_WORDS)   // A + B
#define SMEM_BYTES (2 * STAGE_WORDS * 4)   // double buffered: 73728 B

// Scratch (__device__ globals: allocation-free rule)
__device__ __half g_qh [(size_t)N_Q  * D_IN];
__device__ __half g_kh [(size_t)M_KV * D_IN];
__device__ __half g_vh [(size_t)M_KV * D_IN];
__device__ __half g_Wqh[(size_t)D_OUT * D_IN];
__device__ __half g_Wkh[(size_t)D_OUT * D_IN];
__device__ __half g_Wvh[(size_t)D_OUT * D_IN];
__device__ __half g_Qh [(size_t)N_Q  * D_OUT];
__device__ __half g_Kh [(size_t)M_KV * D_OUT];
__device__ __half g_Vth[(size_t)D_OUT * M_KV];   // V transposed [n][k]
__device__ __half g_P  [(size_t)N_Q  * M_KV];    // UNNORMALIZED exp(scores), fp16

__device__ __forceinline__ uint32_t smem_u32(const void* p) {
    uint32_t a;
    asm("{ .reg .u64 t; cvta.to.shared.u64 t, %1; cvt.u32.u64 %0, t; }" : "=r"(a) : "l"(p));
    return a;
}
#define CP_ASYNC16(dst, src) \
    asm volatile("cp.async.cg.shared.global [%0], [%1], 16;" :: "r"(dst), "l"(src) : "memory")
#define CP_COMMIT()   asm volatile("cp.async.commit_group;" ::: "memory")
#define CP_WAIT(n)    asm volatile("cp.async.wait_group %0;" :: "n"(n) : "memory")

// fp16 mma, fp32 accumulate
__device__ __forceinline__ void mma_f16(float* c, uint32_t a0, uint32_t a1,
                                        uint32_t a2, uint32_t a3,
                                        uint32_t b0, uint32_t b1) {
    asm volatile(
        "mma.sync.aligned.m16n8k16.row.col.f32.f16.f16.f32 "
        "{%0,%1,%2,%3}, {%4,%5,%6,%7}, {%8,%9}, {%0,%1,%2,%3};"
        : "+f"(c[0]), "+f"(c[1]), "+f"(c[2]), "+f"(c[3])
        : "r"(a0), "r"(a1), "r"(a2), "r"(a3), "r"(b0), "r"(b1));
}

__device__ __forceinline__ float hsum2(uint32_t w) {
    float2 f = __half22float2(*(const __half2*)&w);
    return f.x + f.y;
}

// ---------------------------------------------------------------------------
// fp16 NT GEMM: acc[i,j] = sum_k A[i,k]*B[j,k], fp32 accum.
//   4 warps (2x2), warp tile 64x64. CTA tile 128x128.
//   2-stage cp.async double buffer, ONE __syncthreads per k-slab.
//   EPI: 1 = +bias[col]                  -> half out
//        2 = +bias[row]                  -> half out
//        3 = exp(acc*alpha)              -> half out (unnormalized softmax)
//        5 = acc / rowsum(A)             -> float out (rowsum computed in-kernel
//                                           from the A fragments; A must be the
//                                           unnormalized P matrix)
// Requires Mrows%128==0, Ncols%128==0, Kdim%64==0.
// ---------------------------------------------------------------------------
template<int EPI>
__global__ __launch_bounds__(NTHREADS, 2)
void gemm_h(const __half* __restrict__ A, const __half* __restrict__ B,
            const float* __restrict__ bias, void* __restrict__ Cv,
            int Kdim, int Ncols, float alpha)
{
    constexpr bool ROWSUM = (EPI == 5);

    extern __shared__ __align__(16) uint32_t sm[];
    const uint32_t smb = smem_u32(sm);

    const int tid  = threadIdx.x;
    const int wid  = tid >> 5;
    const int lane = tid & 31;
    const int qr   = lane >> 2;     // 0..7
    const int qc   = lane & 3;      // 0..3
    const int wm   = wid >> 1;      // 0..1  (64-row band)
    const int wn   = wid & 1;       // 0..1  (64-col band)
    const int rowBase = blockIdx.y * BM;
    const int colBase = blockIdx.x * BN;

    // loader: 128 threads, 16 rows x 8 chunks per pass, 8 passes per slab
    const int lr  = tid >> 3;       // 0..15
    const int lc8 = tid & 7;        // 16B chunk within the 128-byte row

    float acc[4][8][4];
#pragma unroll
    for (int mt = 0; mt < 4; mt++)
#pragma unroll
        for (int nt = 0; nt < 8; nt++)
#pragma unroll
            for (int j = 0; j < 4; j++) acc[mt][nt][j] = 0.f;

    // per-lane partial row sums of A (P): 2 rows x 4 m-bands
    float rs0[4] = {0.f, 0.f, 0.f, 0.f};
    float rs1[4] = {0.f, 0.f, 0.f, 0.f};

    const int nslab = Kdim / BK;

    const __half* Apl = A + (size_t)(rowBase + lr) * Kdim + lc8 * 8;
    const __half* Bpl = B + (size_t)(colBase + lr) * Kdim + lc8 * 8;
    const size_t astep = (size_t)16 * Kdim;

    const uint32_t dA = smb + (uint32_t)(lr * AST + lc8 * 4) * 4;
    const uint32_t dB = dA + SLAB_WORDS * 4;
    const uint32_t ROWSTEP = 16 * AST * 4;
    const uint32_t STAGEB  = STAGE_WORDS * 4;

    // --- prologue: issue slab 0 into stage 0 ---
#pragma unroll
    for (int p = 0; p < 8; p++) CP_ASYNC16(dA + p * ROWSTEP, Apl + p * astep);
#pragma unroll
    for (int p = 0; p < 8; p++) CP_ASYNC16(dB + p * ROWSTEP, Bpl + p * astep);
    CP_COMMIT();

    for (int s = 0; s < nslab; s++) {
        const int st  = s & 1;
        const int nst = (s + 1) & 1;

        CP_WAIT(0);        // slab s landed
        __syncthreads();   // data visible + compute of s-1 done

        // issue slab s+1 into the other stage (its readers synced above)
        if (s + 1 < nslab) {
            const size_t kb = (size_t)(s + 1) * BK;
            const uint32_t o = (uint32_t)nst * STAGEB;
#pragma unroll
            for (int p = 0; p < 8; p++) CP_ASYNC16(dA + o + p * ROWSTEP, Apl + kb + p * astep);
#pragma unroll
            for (int p = 0; p < 8; p++) CP_ASYNC16(dB + o + p * ROWSTEP, Bpl + kb + p * astep);
            CP_COMMIT();
        }

        const uint32_t* Abuf = sm + st * STAGE_WORDS;
        const uint32_t* Bbuf = Abuf + SLAB_WORDS;
        const uint32_t* Aw = Abuf + (wm * 64 + qr) * AST + qc;
        const uint32_t* Bw = Bbuf + (wn * 64 + qr) * AST + qc;

#pragma unroll
        for (int ks = 0; ks < 4; ks++) {
            uint32_t af[4][4], bf[8][2];
#pragma unroll
            for (int mt = 0; mt < 4; mt++) {
                const uint32_t* pa = Aw + mt * 16 * AST + ks * 8;
                af[mt][0] = pa[0];
                af[mt][1] = pa[8 * AST];
                af[mt][2] = pa[4];
                af[mt][3] = pa[8 * AST + 4];
            }
#pragma unroll
            for (int nt = 0; nt < 8; nt++) {
                const uint32_t* pb = Bw + nt * 8 * AST + ks * 8;
                bf[nt][0] = pb[0];
                bf[nt][1] = pb[4];
            }
            if (ROWSUM) {
                // accumulate partial row sums of the A (P) fragments.
                // per lane: rows r0 = wm*64+mt*16+qr, r1 = r0+8; the 4 qc lanes
                // x 4 ks steps x nslab slabs tile K exactly once.
#pragma unroll
                for (int mt = 0; mt < 4; mt++) {
                    rs0[mt] += hsum2(af[mt][0]) + hsum2(af[mt][2]);
                    rs1[mt] += hsum2(af[mt][1]) + hsum2(af[mt][3]);
                }
            }
#pragma unroll
            for (int mt = 0; mt < 4; mt++)
#pragma unroll
                for (int nt = 0; nt < 8; nt++)
                    mma_f16(acc[mt][nt], af[mt][0], af[mt][1], af[mt][2], af[mt][3],
                            bf[nt][0], bf[nt][1]);
        }
    }

    // --- epilogue ---
#pragma unroll
    for (int mt = 0; mt < 4; mt++) {
        const int r0 = rowBase + wm * 64 + mt * 16 + qr;
        const int r1 = r0 + 8;
        float rb0 = 0.f, rb1 = 0.f;
        if (EPI == 2) { rb0 = bias[r0]; rb1 = bias[r1]; }
        if (ROWSUM) {
            // complete the row sums across the qc quad (lanes qr*4 + 0..3)
            float s0 = rs0[mt], s1 = rs1[mt];
            s0 += __shfl_xor_sync(~0u, s0, 1); s0 += __shfl_xor_sync(~0u, s0, 2);
            s1 += __shfl_xor_sync(~0u, s1, 1); s1 += __shfl_xor_sync(~0u, s1, 2);
            rb0 = 1.0f / s0;
            rb1 = 1.0f / s1;
        }
#pragma unroll
        for (int nt = 0; nt < 8; nt++) {
            const int col = colBase + wn * 64 + nt * 8 + 2 * qc;
            float2 v0, v1;
            v0.x = acc[mt][nt][0]; v0.y = acc[mt][nt][1];
            v1.x = acc[mt][nt][2]; v1.y = acc[mt][nt][3];
            if (EPI == 1) {
                const float b0 = bias[col], b1 = bias[col + 1];
                v0.x += b0; v0.y += b1; v1.x += b0; v1.y += b1;
                __half* Co = (__half*)Cv;
                *(__half2*)(Co + (size_t)r0 * Ncols + col) = __floats2half2_rn(v0.x, v0.y);
                *(__half2*)(Co + (size_t)r1 * Ncols + col) = __floats2half2_rn(v1.x, v1.y);
            } else if (EPI == 2) {
                v0.x += rb0; v0.y += rb0; v1.x += rb1; v1.y += rb1;
                __half* Co = (__half*)Cv;
                *(__half2*)(Co + (size_t)r0 * Ncols + col) = __floats2half2_rn(v0.x, v0.y);
                *(__half2*)(Co + (size_t)r1 * Ncols + col) = __floats2half2_rn(v1.x, v1.y);
            } else if (EPI == 3) {
                // unnormalized softmax numerator: exp(score); no max needed
                // (scores ~ N(0, 0.33), far from fp16/fp32 overflow)
                v0.x = __expf(v0.x * alpha); v0.y = __expf(v0.y * alpha);
                v1.x = __expf(v1.x * alpha); v1.y = __expf(v1.y * alpha);
                __half* Co = (__half*)Cv;
                *(__half2*)(Co + (size_t)r0 * Ncols + col) = __floats2half2_rn(v0.x, v0.y);
                *(__half2*)(Co + (size_t)r1 * Ncols + col) = __floats2half2_rn(v1.x, v1.y);
            } else {  // EPI == 5: normalize by in-kernel rowsum, float out
                v0.x *= rb0; v0.y *= rb0; v1.x *= rb1; v1.y *= rb1;
                float* Co = (float*)Cv;
                *(float2*)(Co + (size_t)r0 * Ncols + col) = v0;
                *(float2*)(Co + (size_t)r1 * Ncols + col) = v1;
            }
        }
    }
}

// ---------------------------------------------------------------------------
// fp32 -> fp16 convert (rn), vectorized
// ---------------------------------------------------------------------------
__global__ __launch_bounds__(256)
void f32_to_f16(const float* __restrict__ src, __half* __restrict__ dst, size_t n)
{
    size_t i = ((size_t)blockIdx.x * 256 + threadIdx.x) * 4;
    const size_t stride = (size_t)gridDim.x * 256 * 4;
    for (; i < n; i += stride) {
        float4 v = *(const float4*)(src + i);
        *(__half2*)(dst + i)     = __floats2half2_rn(v.x, v.y);
        *(__half2*)(dst + i + 2) = __floats2half2_rn(v.z, v.w);
    }
}

// ---------------------------------------------------------------------------
extern "C" void kernel_launch(void* const* d_in, const int* in_sizes, int n_in,
                              void* d_out, int out_size)
{
    const float* query = (const float*)d_in[0];
    const float* key   = (const float*)d_in[1];
    const float* value = (const float*)d_in[2];
    const float* Wq    = (const float*)d_in[3];
    const float* bq    = (const float*)d_in[4];
    const float* Wk    = (const float*)d_in[5];
    const float* bk    = (const float*)d_in[6];
    const float* Wv    = (const float*)d_in[7];
    const float* bv    = (const float*)d_in[8];
    float* out = (float*)d_out;

    __half *qh, *kh, *vh, *Wqh, *Wkh, *Wvh, *Qh, *Kh, *Vth, *Ph;
    cudaGetSymbolAddress((void**)&qh,  g_qh);
    cudaGetSymbolAddress((void**)&kh,  g_kh);
    cudaGetSymbolAddress((void**)&vh,  g_vh);
    cudaGetSymbolAddress((void**)&Wqh, g_Wqh);
    cudaGetSymbolAddress((void**)&Wkh, g_Wkh);
    cudaGetSymbolAddress((void**)&Wvh, g_Wvh);
    cudaGetSymbolAddress((void**)&Qh,  g_Qh);
    cudaGetSymbolAddress((void**)&Kh,  g_Kh);
    cudaGetSymbolAddress((void**)&Vth, g_Vth);
    cudaGetSymbolAddress((void**)&Ph,  g_P);

    cudaFuncSetAttribute(gemm_h<1>, cudaFuncAttributeMaxDynamicSharedMemorySize, SMEM_BYTES);
    cudaFuncSetAttribute(gemm_h<2>, cudaFuncAttributeMaxDynamicSharedMemorySize, SMEM_BYTES);
    cudaFuncSetAttribute(gemm_h<3>, cudaFuncAttributeMaxDynamicSharedMemorySize, SMEM_BYTES);
    cudaFuncSetAttribute(gemm_h<5>, cudaFuncAttributeMaxDynamicSharedMemorySize, SMEM_BYTES);

    const float scale = 1.0f / 32.0f;   // 1/sqrt(1024), key *input* dim
    dim3 blk(NTHREADS);

    // Convert inputs and weights to fp16
    const size_t nin = (size_t)N_Q * D_IN;
    const size_t nw  = (size_t)D_OUT * D_IN;
    f32_to_f16<<<2048, 256>>>(query, qh, nin);
    f32_to_f16<<<2048, 256>>>(key,   kh, nin);
    f32_to_f16<<<2048, 256>>>(value, vh, nin);
    f32_to_f16<<<1024, 256>>>(Wq, Wqh, nw);
    f32_to_f16<<<1024, 256>>>(Wk, Wkh, nw);
    f32_to_f16<<<1024, 256>>>(Wv, Wvh, nw);

    // Q = query @ Wq^T + bq : [8192,1024] half
    gemm_h<1><<<dim3(D_OUT / BN, N_Q / BM), blk, SMEM_BYTES>>>(qh, Wqh, bq, Qh, D_IN, D_OUT, 1.f);
    // K = key @ Wk^T + bk : half
    gemm_h<1><<<dim3(D_OUT / BN, M_KV / BM), blk, SMEM_BYTES>>>(kh, Wkh, bk, Kh, D_IN, D_OUT, 1.f);
    // Vt = Wv @ value^T + bv(row) : [1024, 8192] half
    gemm_h<2><<<dim3(M_KV / BN, D_OUT / BM), blk, SMEM_BYTES>>>(Wvh, vh, bv, Vth, D_IN, M_KV, 1.f);
    // P = exp((Q @ K^T) * scale) : [8192, 8192] half, unnormalized
    gemm_h<3><<<dim3(M_KV / BN, N_Q / BM), blk, SMEM_BYTES>>>(Qh, Kh, nullptr, Ph, D_OUT, M_KV, scale);
    // out = (P @ Vt^T) / rowsum(P) : [8192, 1024] fp32 — rowsum fused in-kernel
    gemm_h<5><<<dim3(D_OUT / BN, N_Q / BM), blk, SMEM_BYTES>>>(Ph, Vth, nullptr, out, M_KV, D_OUT, 1.f);
}

// round 16
// speedup vs baseline: 1.0563x; 1.0563x over previous
#include <cuda_runtime.h>
#include <cuda_fp16.h>
#include <cstdint>

// Problem dims (fixed)
#define N_Q   8192
#define M_KV  8192
#define D_IN  1024
#define D_OUT 1024

// GEMM tiling (fp16 operands), 4 warps of 64x64
#define BM 128
#define BN 128
#define BK 64                          // halves per k-slab = 128 bytes/row
#define NTHREADS 128
#define AST 36                         // smem row stride in 32-bit words (32 data + 4 pad)
#define SLAB_WORDS (BM * AST)
#define STAGE_WORDS (2 * SLAB_WORDS)   // A + B
#define SMEM_BYTES (2 * STAGE_WORDS * 4 + 1024)   // stages + epilogue rowsum scratch

#define NCT (M_KV / BN)                // 64 column tiles per S row

// Scratch (__device__ globals: allocation-free rule)
__device__ __half g_qh [(size_t)N_Q  * D_IN];
__device__ __half g_kh [(size_t)M_KV * D_IN];
__device__ __half g_vh [(size_t)M_KV * D_IN];
__device__ __half g_Wqh[(size_t)D_OUT * D_IN];
__device__ __half g_Wkh[(size_t)D_OUT * D_IN];
__device__ __half g_Wvh[(size_t)D_OUT * D_IN];
__device__ __half g_Qh [(size_t)N_Q  * D_OUT];
__device__ __half g_Kh [(size_t)M_KV * D_OUT];
__device__ __half g_Vth[(size_t)D_OUT * M_KV];   // V transposed [n][k]
__device__ __half g_P  [(size_t)N_Q  * M_KV];    // UNNORMALIZED exp(scores), fp16
__device__ float  g_part[(size_t)N_Q * NCT];     // per-(row, colTile) partial sums
__device__ float  g_inv[N_Q];                    // 1 / rowsum

__device__ __forceinline__ uint32_t smem_u32(const void* p) {
    uint32_t a;
    asm("{ .reg .u64 t; cvta.to.shared.u64 t, %1; cvt.u32.u64 %0, t; }" : "=r"(a) : "l"(p));
    return a;
}
#define CP_ASYNC16(dst, src) \
    asm volatile("cp.async.cg.shared.global [%0], [%1], 16;" :: "r"(dst), "l"(src) : "memory")
#define CP_COMMIT()   asm volatile("cp.async.commit_group;" ::: "memory")
#define CP_WAIT(n)    asm volatile("cp.async.wait_group %0;" :: "n"(n) : "memory")

// fp16 mma, fp32 accumulate
__device__ __forceinline__ void mma_f16(float* c, uint32_t a0, uint32_t a1,
                                        uint32_t a2, uint32_t a3,
                                        uint32_t b0, uint32_t b1) {
    asm volatile(
        "mma.sync.aligned.m16n8k16.row.col.f32.f16.f16.f32 "
        "{%0,%1,%2,%3}, {%4,%5,%6,%7}, {%8,%9}, {%0,%1,%2,%3};"
        : "+f"(c[0]), "+f"(c[1]), "+f"(c[2]), "+f"(c[3])
        : "r"(a0), "r"(a1), "r"(a2), "r"(a3), "r"(b0), "r"(b1));
}

// ---------------------------------------------------------------------------
// fp16 NT GEMM: acc[i,j] = sum_k A[i,k]*B[j,k], fp32 accum.
//   4 warps (2x2), warp tile 64x64. CTA tile 128x128.
//   2-stage cp.async double buffer, ONE __syncthreads per k-slab.
//   EPI: 1 = +aux[col]         -> half out
//        2 = +aux[row]         -> half out
//        3 = exp(acc*alpha)    -> half out; ALSO writes per-tile row sums to
//                                 aux[row * NCT + blockIdx.x] (epilogue-only)
//        4 = acc * aux[row]    -> float out (row scale)
// Requires Mrows%128==0, Ncols%128==0, Kdim%64==0.
// ---------------------------------------------------------------------------
template<int EPI>
__global__ __launch_bounds__(NTHREADS, 2)
void gemm_h(const __half* __restrict__ A, const __half* __restrict__ B,
            const float* __restrict__ aux, void* __restrict__ Cv,
            int Kdim, int Ncols, float alpha)
{
    extern __shared__ __align__(16) uint32_t sm[];
    const uint32_t smb = smem_u32(sm);

    const int tid  = threadIdx.x;
    const int wid  = tid >> 5;
    const int lane = tid & 31;
    const int qr   = lane >> 2;     // 0..7
    const int qc   = lane & 3;      // 0..3
    const int wm   = wid >> 1;      // 0..1  (64-row band)
    const int wn   = wid & 1;       // 0..1  (64-col band)
    const int rowBase = blockIdx.y * BM;
    const int colBase = blockIdx.x * BN;

    // loader: 128 threads, 16 rows x 8 chunks per pass, 8 passes per slab
    const int lr  = tid >> 3;       // 0..15
    const int lc8 = tid & 7;        // 16B chunk within the 128-byte row

    float acc[4][8][4];
#pragma unroll
    for (int mt = 0; mt < 4; mt++)
#pragma unroll
        for (int nt = 0; nt < 8; nt++)
#pragma unroll
            for (int j = 0; j < 4; j++) acc[mt][nt][j] = 0.f;

    const int nslab = Kdim / BK;

    const __half* Apl = A + (size_t)(rowBase + lr) * Kdim + lc8 * 8;
    const __half* Bpl = B + (size_t)(colBase + lr) * Kdim + lc8 * 8;
    const size_t astep = (size_t)16 * Kdim;

    const uint32_t dA = smb + (uint32_t)(lr * AST + lc8 * 4) * 4;
    const uint32_t dB = dA + SLAB_WORDS * 4;
    const uint32_t ROWSTEP = 16 * AST * 4;
    const uint32_t STAGEB  = STAGE_WORDS * 4;

    // --- prologue: issue slab 0 into stage 0 ---
#pragma unroll
    for (int p = 0; p < 8; p++) CP_ASYNC16(dA + p * ROWSTEP, Apl + p * astep);
#pragma unroll
    for (int p = 0; p < 8; p++) CP_ASYNC16(dB + p * ROWSTEP, Bpl + p * astep);
    CP_COMMIT();

    for (int s = 0; s < nslab; s++) {
        const int st  = s & 1;
        const int nst = (s + 1) & 1;

        CP_WAIT(0);        // slab s landed
        __syncthreads();   // data visible + compute of s-1 done

        if (s + 1 < nslab) {
            const size_t kb = (size_t)(s + 1) * BK;
            const uint32_t o = (uint32_t)nst * STAGEB;
#pragma unroll
            for (int p = 0; p < 8; p++) CP_ASYNC16(dA + o + p * ROWSTEP, Apl + kb + p * astep);
#pragma unroll
            for (int p = 0; p < 8; p++) CP_ASYNC16(dB + o + p * ROWSTEP, Bpl + kb + p * astep);
            CP_COMMIT();
        }

        const uint32_t* Abuf = sm + st * STAGE_WORDS;
        const uint32_t* Bbuf = Abuf + SLAB_WORDS;
        const uint32_t* Aw = Abuf + (wm * 64 + qr) * AST + qc;
        const uint32_t* Bw = Bbuf + (wn * 64 + qr) * AST + qc;

#pragma unroll
        for (int ks = 0; ks < 4; ks++) {
            uint32_t af[4][4], bf[8][2];
#pragma unroll
            for (int mt = 0; mt < 4; mt++) {
                const uint32_t* pa = Aw + mt * 16 * AST + ks * 8;
                af[mt][0] = pa[0];
                af[mt][1] = pa[8 * AST];
                af[mt][2] = pa[4];
                af[mt][3] = pa[8 * AST + 4];
            }
#pragma unroll
            for (int nt = 0; nt < 8; nt++) {
                const uint32_t* pb = Bw + nt * 8 * AST + ks * 8;
                bf[nt][0] = pb[0];
                bf[nt][1] = pb[4];
            }
#pragma unroll
            for (int mt = 0; mt < 4; mt++)
#pragma unroll
                for (int nt = 0; nt < 8; nt++)
                    mma_f16(acc[mt][nt], af[mt][0], af[mt][1], af[mt][2], af[mt][3],
                            bf[nt][0], bf[nt][1]);
        }
    }

    // epilogue rowsum scratch lives ABOVE the stage buffers (no race with
    // lagging warps still reading the stages)
    float* rsum = (float*)(sm + 2 * STAGE_WORDS);   // [2][128]

    // --- epilogue ---
#pragma unroll
    for (int mt = 0; mt < 4; mt++) {
        const int r0 = rowBase + wm * 64 + mt * 16 + qr;
        const int r1 = r0 + 8;
        float rb0 = 0.f, rb1 = 0.f;
        if (EPI == 2 || EPI == 4) { rb0 = aux[r0]; rb1 = aux[r1]; }
        float ps0 = 0.f, ps1 = 0.f;   // EPI 3: per-thread row partials
#pragma unroll
        for (int nt = 0; nt < 8; nt++) {
            const int col = colBase + wn * 64 + nt * 8 + 2 * qc;
            float2 v0, v1;
            v0.x = acc[mt][nt][0]; v0.y = acc[mt][nt][1];
            v1.x = acc[mt][nt][2]; v1.y = acc[mt][nt][3];
            if (EPI == 1) {
                const float b0 = aux[col], b1 = aux[col + 1];
                v0.x += b0; v0.y += b1; v1.x += b0; v1.y += b1;
                __half* Co = (__half*)Cv;
                *(__half2*)(Co + (size_t)r0 * Ncols + col) = __floats2half2_rn(v0.x, v0.y);
                *(__half2*)(Co + (size_t)r1 * Ncols + col) = __floats2half2_rn(v1.x, v1.y);
            } else if (EPI == 2) {
                v0.x += rb0; v0.y += rb0; v1.x += rb1; v1.y += rb1;
                __half* Co = (__half*)Cv;
                *(__half2*)(Co + (size_t)r0 * Ncols + col) = __floats2half2_rn(v0.x, v0.y);
                *(__half2*)(Co + (size_t)r1 * Ncols + col) = __floats2half2_rn(v1.x, v1.y);
            } else if (EPI == 3) {
                // unnormalized softmax numerator: exp(score); no max needed
                // (scores ~ N(0, 0.33), far from overflow)
                v0.x = __expf(v0.x * alpha); v0.y = __expf(v0.y * alpha);
                v1.x = __expf(v1.x * alpha); v1.y = __expf(v1.y * alpha);
                ps0 += v0.x + v0.y;
                ps1 += v1.x + v1.y;
                __half* Co = (__half*)Cv;
                *(__half2*)(Co + (size_t)r0 * Ncols + col) = __floats2half2_rn(v0.x, v0.y);
                *(__half2*)(Co + (size_t)r1 * Ncols + col) = __floats2half2_rn(v1.x, v1.y);
            } else {  // EPI == 4: row scale, float out
                v0.x *= rb0; v0.y *= rb0; v1.x *= rb1; v1.y *= rb1;
                float* Co = (float*)Cv;
                *(float2*)(Co + (size_t)r0 * Ncols + col) = v0;
                *(float2*)(Co + (size_t)r1 * Ncols + col) = v1;
            }
        }
        if (EPI == 3) {
            // reduce across the qc quad; lane qc==0 holds the 64-col band sum
            ps0 += __shfl_xor_sync(~0u, ps0, 1); ps0 += __shfl_xor_sync(~0u, ps0, 2);
            ps1 += __shfl_xor_sync(~0u, ps1, 1); ps1 += __shfl_xor_sync(~0u, ps1, 2);
            if (qc == 0) {
                const int lrow = wm * 64 + mt * 16 + qr;
                rsum[wn * 128 + lrow]     = ps0;
                rsum[wn * 128 + lrow + 8] = ps1;
            }
        }
    }
    if (EPI == 3) {
        __syncthreads();
        if (tid < 128) {
            float tot = rsum[tid] + rsum[128 + tid];
            float* aux_out = const_cast<float*>(aux);
            aux_out[(size_t)(rowBase + tid) * NCT + blockIdx.x] = tot;
        }
    }
}

// ---------------------------------------------------------------------------
// fp32 -> fp16 convert (rn), vectorized
// ---------------------------------------------------------------------------
__global__ __launch_bounds__(256)
void f32_to_f16(const float* __restrict__ src, __half* __restrict__ dst, size_t n)
{
    size_t i = ((size_t)blockIdx.x * 256 + threadIdx.x) * 4;
    const size_t stride = (size_t)gridDim.x * 256 * 4;
    for (; i < n; i += stride) {
        float4 v = *(const float4*)(src + i);
        *(__half2*)(dst + i)     = __floats2half2_rn(v.x, v.y);
        *(__half2*)(dst + i + 2) = __floats2half2_rn(v.z, v.w);
    }
}

// ---------------------------------------------------------------------------
// inv[row] = 1 / sum_{ct} partial[row][ct]   (fixed order -> deterministic)
// ---------------------------------------------------------------------------
__global__ __launch_bounds__(256)
void rowinv(const float* __restrict__ partial, float* __restrict__ inv)
{
    const int row = blockIdx.x * 256 + threadIdx.x;
    const float* p = partial + (size_t)row * NCT;
    float s = 0.f;
#pragma unroll
    for (int i = 0; i < NCT; i += 4) {
        float4 v = *(const float4*)(p + i);
        s += (v.x + v.y) + (v.z + v.w);
    }
    inv[row] = 1.0f / s;
}

// ---------------------------------------------------------------------------
extern "C" void kernel_launch(void* const* d_in, const int* in_sizes, int n_in,
                              void* d_out, int out_size)
{
    const float* query = (const float*)d_in[0];
    const float* key   = (const float*)d_in[1];
    const float* value = (const float*)d_in[2];
    const float* Wq    = (const float*)d_in[3];
    const float* bq    = (const float*)d_in[4];
    const float* Wk    = (const float*)d_in[5];
    const float* bk    = (const float*)d_in[6];
    const float* Wv    = (const float*)d_in[7];
    const float* bv    = (const float*)d_in[8];
    float* out = (float*)d_out;

    __half *qh, *kh, *vh, *Wqh, *Wkh, *Wvh, *Qh, *Kh, *Vth, *Ph;
    float *parts, *invs;
    cudaGetSymbolAddress((void**)&qh,  g_qh);
    cudaGetSymbolAddress((void**)&kh,  g_kh);
    cudaGetSymbolAddress((void**)&vh,  g_vh);
    cudaGetSymbolAddress((void**)&Wqh, g_Wqh);
    cudaGetSymbolAddress((void**)&Wkh, g_Wkh);
    cudaGetSymbolAddress((void**)&Wvh, g_Wvh);
    cudaGetSymbolAddress((void**)&Qh,  g_Qh);
    cudaGetSymbolAddress((void**)&Kh,  g_Kh);
    cudaGetSymbolAddress((void**)&Vth, g_Vth);
    cudaGetSymbolAddress((void**)&Ph,  g_P);
    cudaGetSymbolAddress((void**)&parts, g_part);
    cudaGetSymbolAddress((void**)&invs,  g_inv);

    cudaFuncSetAttribute(gemm_h<1>, cudaFuncAttributeMaxDynamicSharedMemorySize, SMEM_BYTES);
    cudaFuncSetAttribute(gemm_h<2>, cudaFuncAttributeMaxDynamicSharedMemorySize, SMEM_BYTES);
    cudaFuncSetAttribute(gemm_h<3>, cudaFuncAttributeMaxDynamicSharedMemorySize, SMEM_BYTES);
    cudaFuncSetAttribute(gemm_h<4>, cudaFuncAttributeMaxDynamicSharedMemorySize, SMEM_BYTES);

    const float scale = 1.0f / 32.0f;   // 1/sqrt(1024), key *input* dim
    dim3 blk(NTHREADS);

    // Convert inputs and weights to fp16
    const size_t nin = (size_t)N_Q * D_IN;
    const size_t nw  = (size_t)D_OUT * D_IN;
    f32_to_f16<<<2048, 256>>>(query, qh, nin);
    f32_to_f16<<<2048, 256>>>(key,   kh, nin);
    f32_to_f16<<<2048, 256>>>(value, vh, nin);
    f32_to_f16<<<1024, 256>>>(Wq, Wqh, nw);
    f32_to_f16<<<1024, 256>>>(Wk, Wkh, nw);
    f32_to_f16<<<1024, 256>>>(Wv, Wvh, nw);

    // Q = query @ Wq^T + bq : [8192,1024] half
    gemm_h<1><<<dim3(D_OUT / BN, N_Q / BM), blk, SMEM_BYTES>>>(qh, Wqh, bq, Qh, D_IN, D_OUT, 1.f);
    // K = key @ Wk^T + bk : half
    gemm_h<1><<<dim3(D_OUT / BN, M_KV / BM), blk, SMEM_BYTES>>>(kh, Wkh, bk, Kh, D_IN, D_OUT, 1.f);
    // Vt = Wv @ value^T + bv(row) : [1024, 8192] half
    gemm_h<2><<<dim3(M_KV / BN, D_OUT / BM), blk, SMEM_BYTES>>>(Wvh, vh, bv, Vth, D_IN, M_KV, 1.f);
    // P = exp((Q @ K^T) * scale) : [8192, 8192] half + per-tile row partials
    gemm_h<3><<<dim3(M_KV / BN, N_Q / BM), blk, SMEM_BYTES>>>(Qh, Kh, parts, Ph, D_OUT, M_KV, scale);
    // inv[row] = 1 / rowsum  (reads 2 MB of partials, deterministic)
    rowinv<<<N_Q / 256, 256>>>(parts, invs);
    // out = (P @ Vt^T) * inv[row] : [8192, 1024] fp32
    gemm_h<4><<<dim3(D_OUT / BN, N_Q / BM), blk, SMEM_BYTES>>>(Ph, Vth, invs, out, M_KV, D_OUT, 1.f);
}